// round 6
// baseline (speedup 1.0000x reference)
#include <cuda_runtime.h>
#include <math.h>

// WindowAttention: B=32, 64x64, C=256, ws=8 -> 2048 windows of 64 tokens.
// One CTA (256 threads) per window. fp32 with packed f32x2 FMA (FFMA2).
// LN affines for q/k/v folded into weights by prep kernels each launch.

#define EPS 1e-5f

// ---- device-global scratch (allowed; no allocations) ----
__device__ float g_Wt[256 * 768];    // Wt[k][col] = w_in[col][k] * g_branch[k]   (k-major)
__device__ float g_bias[768];        // b_in[col] + sum_k w_in[col][k]*b_branch[k]
__device__ float g_WoT[256 * 256];   // WoT[k][j] = w_out[j][k]                   (k-major)

typedef unsigned long long u64;

__device__ __forceinline__ u64 pk2(float lo, float hi) {
    u64 r; asm("mov.b64 %0, {%1, %2};" : "=l"(r) : "f"(lo), "f"(hi)); return r;
}
__device__ __forceinline__ void upk2(u64 v, float& lo, float& hi) {
    asm("mov.b64 {%0, %1}, %2;" : "=f"(lo), "=f"(hi) : "l"(v));
}
__device__ __forceinline__ void fma2(u64& d, u64 a, u64 b) {
    asm("fma.rn.f32x2 %0, %1, %2, %3;" : "=l"(d) : "l"(a), "l"(b), "l"(d));
}

// ---- prep: fold LN affine into packed in_proj, transpose to k-major ----
__global__ void prep_w_kernel(const float* __restrict__ w_in, const float* __restrict__ b_in,
                              const float* __restrict__ g_q, const float* __restrict__ b_q,
                              const float* __restrict__ g_k, const float* __restrict__ b_k,
                              const float* __restrict__ g_v, const float* __restrict__ b_v) {
    __shared__ float red[8];
    int col = blockIdx.x;       // 0..767
    int k   = threadIdx.x;      // 0..255
    const float* g; const float* b;
    if (col < 256)      { g = g_q; b = b_q; }
    else if (col < 512) { g = g_k; b = b_k; }
    else                { g = g_v; b = b_v; }
    float w = w_in[col * 256 + k];
    g_Wt[k * 768 + col] = w * g[k];
    float p = w * b[k];
    #pragma unroll
    for (int o = 16; o; o >>= 1) p += __shfl_xor_sync(0xffffffffu, p, o);
    if ((k & 31) == 0) red[k >> 5] = p;
    __syncthreads();
    if (k < 8) {
        float s = red[k];
        #pragma unroll
        for (int o = 4; o; o >>= 1) s += __shfl_xor_sync(0xffu, s, o);
        if (k == 0) g_bias[col] = b_in[col] + s;
    }
}

__global__ void prep_wo_kernel(const float* __restrict__ w_out) {
    int idx = blockIdx.x * 256 + threadIdx.x;   // 65536 elements
    int j = idx >> 8, k = idx & 255;
    g_WoT[k * 256 + j] = w_out[idx];
}

// ---- main fused window-attention kernel ----
__global__ __launch_bounds__(256, 1)
void win_attn_kernel(const float* __restrict__ x, const float* __restrict__ b_out,
                     const float* __restrict__ g_o, const float* __restrict__ b_o,
                     float* __restrict__ y) {
    extern __shared__ float sm[];
    float* xn   = sm;                   // [64][256] normalized input (later residual r)
    float* obuf = xn + 64 * 256;        // [64][256] attention output
    float* q2   = obuf + 64 * 256;      // [64][65]  2 heads (32+32 cols), pad 65
    float* k2   = q2 + 64 * 65;         // [64][65]
    float* v2   = k2 + 64 * 65;         // [64][65]
    float* sc   = v2 + 64 * 65;         // [64][64]  scores / attn
    float* mA   = sc + 64 * 64;         // [64] row mean of x
    float* sA   = mA + 64;              // [64] row std  of x

    const int tid  = threadIdx.x;
    const int w    = tid >> 5;          // warp 0..7, owns rows 8w..8w+7
    const int tx   = tid & 31;
    const int row0 = w * 8;

    const int win = blockIdx.x;
    const int b   = win >> 6;
    const int wh  = (win >> 3) & 7;
    const int ww  = win & 7;
    const int gbase = ((b * 64 + wh * 8) * 64 + ww * 8) * 256;

    // ---- load window (coalesced: thread = channel) ----
    for (int t = 0; t < 64; ++t) {
        int off = gbase + (t >> 3) * (64 * 256) + (t & 7) * 256;
        xn[t * 256 + tid] = x[off + tid];
    }
    __syncthreads();

    // ---- LN stats + normalize in place (warp-local rows) ----
    for (int i = 0; i < 8; ++i) {
        int r = row0 + i;
        float s = 0.f, ss = 0.f;
        #pragma unroll
        for (int c = tx; c < 256; c += 32) { float vv = xn[r * 256 + c]; s += vv; ss += vv * vv; }
        #pragma unroll
        for (int o = 16; o; o >>= 1) { s  += __shfl_xor_sync(0xffffffffu, s,  o);
                                       ss += __shfl_xor_sync(0xffffffffu, ss, o); }
        float mean = s * (1.f / 256.f);
        float var  = ss * (1.f / 256.f) - mean * mean;
        float sd   = sqrtf(var + EPS);
        float inv  = 1.f / sd;
        if (tx == 0) { mA[r] = mean; sA[r] = sd; }
        #pragma unroll
        for (int c = tx; c < 256; c += 32) xn[r * 256 + c] = (xn[r * 256 + c] - mean) * inv;
    }
    __syncthreads();

    const float invsqd = 0.17677669529663689f;  // 1/sqrt(32)

    for (int hp = 0; hp < 4; ++hp) {
        const int hA = hp, hB = hp + 4;
        // ---- GEMM1: q,k,v for heads hA,hB.  out[64][6*32], K=256 ----
        {
            const int cqA = hA * 32 + tx, ckA = 256 + cqA, cvA = 512 + cqA;
            const int cqB = hB * 32 + tx, ckB = 256 + cqB, cvB = 512 + cqB;
            u64 acc[4][6];
            #pragma unroll
            for (int p = 0; p < 4; ++p)
                #pragma unroll
                for (int j = 0; j < 6; ++j) acc[p][j] = 0ULL;

            #pragma unroll 4
            for (int kk = 0; kk < 256; ++kk) {
                const float* wr = g_Wt + kk * 768;
                float wqA = wr[cqA], wkA = wr[ckA], wvA = wr[cvA];
                float wqB = wr[cqB], wkB = wr[ckB], wvB = wr[cvB];
                u64 W0 = pk2(wqA, wqA), W1 = pk2(wkA, wkA), W2 = pk2(wvA, wvA);
                u64 W3 = pk2(wqB, wqB), W4 = pk2(wkB, wkB), W5 = pk2(wvB, wvB);
                #pragma unroll
                for (int p = 0; p < 4; ++p) {
                    const float* ar = xn + (row0 + 2 * p) * 256 + kk;
                    u64 A = pk2(ar[0], ar[256]);
                    fma2(acc[p][0], A, W0); fma2(acc[p][1], A, W1); fma2(acc[p][2], A, W2);
                    fma2(acc[p][3], A, W3); fma2(acc[p][4], A, W4); fma2(acc[p][5], A, W5);
                }
            }
            float bqA = g_bias[cqA], bkA = g_bias[ckA], bvA = g_bias[cvA];
            float bqB = g_bias[cqB], bkB = g_bias[ckB], bvB = g_bias[cvB];
            #pragma unroll
            for (int p = 0; p < 4; ++p) {
                int r0 = row0 + 2 * p, r1 = r0 + 1;
                float lo, hi;
                upk2(acc[p][0], lo, hi);
                q2[r0 * 65 + tx] = (lo + bqA) * invsqd;  q2[r1 * 65 + tx] = (hi + bqA) * invsqd;
                upk2(acc[p][1], lo, hi);
                k2[r0 * 65 + tx] = lo + bkA;             k2[r1 * 65 + tx] = hi + bkA;
                upk2(acc[p][2], lo, hi);
                v2[r0 * 65 + tx] = lo + bvA;             v2[r1 * 65 + tx] = hi + bvA;
                upk2(acc[p][3], lo, hi);
                q2[r0 * 65 + 32 + tx] = (lo + bqB) * invsqd;  q2[r1 * 65 + 32 + tx] = (hi + bqB) * invsqd;
                upk2(acc[p][4], lo, hi);
                k2[r0 * 65 + 32 + tx] = lo + bkB;        k2[r1 * 65 + 32 + tx] = hi + bkB;
                upk2(acc[p][5], lo, hi);
                v2[r0 * 65 + 32 + tx] = lo + bvB;        v2[r1 * 65 + 32 + tx] = hi + bvB;
            }
        }
        __syncthreads();   // k2/v2 read cross-warp below

        #pragma unroll
        for (int s = 0; s < 2; ++s) {
            const int hcol = (s == 0 ? hA : hB) * 32;
            const int kc0  = s * 32;
            // ---- GEMM2: scores[64][64], K=32 ----
            {
                u64 acc[4][2];
                #pragma unroll
                for (int p = 0; p < 4; ++p) { acc[p][0] = 0ULL; acc[p][1] = 0ULL; }
                #pragma unroll 4
                for (int kk = 0; kk < 32; ++kk) {
                    int kc = kc0 + kk;
                    float b0 = k2[tx * 65 + kc];
                    float b1 = k2[(tx + 32) * 65 + kc];
                    u64 B0 = pk2(b0, b0), B1 = pk2(b1, b1);
                    #pragma unroll
                    for (int p = 0; p < 4; ++p) {
                        const float* qr = q2 + (row0 + 2 * p) * 65 + kc;
                        u64 A = pk2(qr[0], qr[65]);
                        fma2(acc[p][0], A, B0); fma2(acc[p][1], A, B1);
                    }
                }
                #pragma unroll
                for (int p = 0; p < 4; ++p) {
                    int r0 = row0 + 2 * p;
                    float lo, hi;
                    upk2(acc[p][0], lo, hi);
                    sc[r0 * 64 + tx] = lo;        sc[(r0 + 1) * 64 + tx] = hi;
                    upk2(acc[p][1], lo, hi);
                    sc[r0 * 64 + 32 + tx] = lo;   sc[(r0 + 1) * 64 + 32 + tx] = hi;
                }
            }
            __syncwarp();
            // ---- softmax over rows (warp-local) ----
            #pragma unroll
            for (int i = 0; i < 8; ++i) {
                int r = row0 + i;
                float s0 = sc[r * 64 + tx], s1 = sc[r * 64 + 32 + tx];
                float mx = fmaxf(s0, s1);
                #pragma unroll
                for (int o = 16; o; o >>= 1) mx = fmaxf(mx, __shfl_xor_sync(0xffffffffu, mx, o));
                float e0 = __expf(s0 - mx), e1 = __expf(s1 - mx);
                float sum = e0 + e1;
                #pragma unroll
                for (int o = 16; o; o >>= 1) sum += __shfl_xor_sync(0xffffffffu, sum, o);
                float inv = 1.f / sum;
                sc[r * 64 + tx] = e0 * inv; sc[r * 64 + 32 + tx] = e1 * inv;
            }
            __syncwarp();
            // ---- GEMM3: o_h[64][32] = attn @ v, K=64 ----
            {
                u64 acc[4] = {0ULL, 0ULL, 0ULL, 0ULL};
                #pragma unroll 4
                for (int l = 0; l < 64; ++l) {
                    float bv = v2[l * 65 + kc0 + tx];
                    u64 B = pk2(bv, bv);
                    #pragma unroll
                    for (int p = 0; p < 4; ++p) {
                        const float* arr = sc + (row0 + 2 * p) * 64 + l;
                        u64 A = pk2(arr[0], arr[64]);
                        fma2(acc[p], A, B);
                    }
                }
                #pragma unroll
                for (int p = 0; p < 4; ++p) {
                    int r0 = row0 + 2 * p;
                    float lo, hi; upk2(acc[p], lo, hi);
                    obuf[r0 * 256 + hcol + tx]       = lo;
                    obuf[(r0 + 1) * 256 + hcol + tx] = hi;
                }
            }
            __syncwarp();
        }
        __syncthreads();   // before next hp overwrites q2/k2/v2
    }

    // ---- out projection + residual (warp-local rows) ----
    {
        u64 acc[4][8];
        #pragma unroll
        for (int p = 0; p < 4; ++p)
            #pragma unroll
            for (int j = 0; j < 8; ++j) acc[p][j] = 0ULL;
        #pragma unroll 2
        for (int kk = 0; kk < 256; ++kk) {
            const float* wr = g_WoT + kk * 256 + tx;
            u64 W[8];
            #pragma unroll
            for (int j = 0; j < 8; ++j) { float wv = wr[j * 32]; W[j] = pk2(wv, wv); }
            #pragma unroll
            for (int p = 0; p < 4; ++p) {
                const float* ar = obuf + (row0 + 2 * p) * 256 + kk;
                u64 A = pk2(ar[0], ar[256]);
                #pragma unroll
                for (int j = 0; j < 8; ++j) fma2(acc[p][j], A, W[j]);
            }
        }
        #pragma unroll
        for (int p = 0; p < 4; ++p) {
            int r0 = row0 + 2 * p, r1 = r0 + 1;
            float m0 = mA[r0], s0 = sA[r0], m1 = mA[r1], s1 = sA[r1];
            #pragma unroll
            for (int j = 0; j < 8; ++j) {
                int c = tx + j * 32;
                float lo, hi; upk2(acc[p][j], lo, hi);
                float bo = b_out[c];
                xn[r0 * 256 + c] = xn[r0 * 256 + c] * s0 + m0 + lo + bo;   // xw + z
                xn[r1 * 256 + c] = xn[r1 * 256 + c] * s1 + m1 + hi + bo;
            }
        }
    }
    __syncwarp();

    // ---- final LN + store (warp-local rows, coalesced) ----
    for (int i = 0; i < 8; ++i) {
        int r = row0 + i;
        float s = 0.f, ss = 0.f;
        #pragma unroll
        for (int c = tx; c < 256; c += 32) { float vv = xn[r * 256 + c]; s += vv; ss += vv * vv; }
        #pragma unroll
        for (int o = 16; o; o >>= 1) { s  += __shfl_xor_sync(0xffffffffu, s,  o);
                                       ss += __shfl_xor_sync(0xffffffffu, ss, o); }
        float mean = s * (1.f / 256.f);
        float var  = ss * (1.f / 256.f) - mean * mean;
        float inv  = rsqrtf(var + EPS);
        int off = gbase + (r >> 3) * (64 * 256) + (r & 7) * 256;
        #pragma unroll
        for (int c = tx; c < 256; c += 32) {
            float vv = (xn[r * 256 + c] - mean) * inv;
            y[off + c] = vv * g_o[c] + b_o[c];
        }
    }
}

static const int SMEM_BYTES = (64 * 256 * 2 + 64 * 65 * 3 + 64 * 64 + 128) * (int)sizeof(float);

extern "C" void kernel_launch(void* const* d_in, const int* in_sizes, int n_in,
                              void* d_out, int out_size) {
    (void)in_sizes; (void)n_in; (void)out_size;
    const float* x     = (const float*)d_in[0];
    const float* w_in  = (const float*)d_in[1];
    const float* b_in  = (const float*)d_in[2];
    const float* w_out = (const float*)d_in[3];
    const float* b_out = (const float*)d_in[4];
    const float* g_q   = (const float*)d_in[5];
    const float* b_q   = (const float*)d_in[6];
    const float* g_k   = (const float*)d_in[7];
    const float* b_k   = (const float*)d_in[8];
    const float* g_v   = (const float*)d_in[9];
    const float* b_v   = (const float*)d_in[10];
    const float* g_o   = (const float*)d_in[11];
    const float* b_o   = (const float*)d_in[12];
    float* y = (float*)d_out;

    cudaFuncSetAttribute(win_attn_kernel, cudaFuncAttributeMaxDynamicSharedMemorySize, SMEM_BYTES);

    prep_w_kernel<<<768, 256>>>(w_in, b_in, g_q, b_q, g_k, b_k, g_v, b_v);
    prep_wo_kernel<<<256, 256>>>(w_out);
    win_attn_kernel<<<2048, 256, SMEM_BYTES>>>(x, b_out, g_o, b_o, y);
}

// round 7
// speedup vs baseline: 1.6005x; 1.6005x over previous
#include <cuda_runtime.h>
#include <math.h>

// WindowAttention: B=32, 64x64, C=256, ws=8 -> 2048 windows of 64 tokens.
// One CTA (256 threads) per window. fp32 FFMA2 with:
//  - pair-interleaved A-side smem layouts (LDS.64 operands, STS.64 epilogues)
//  - double-buffered smem weight tiles (kills hot-loop LDG pressure)
//  - q-scale folded into prepped weights.

#define EPS 1e-5f

__device__ float g_Wt[256 * 768];    // Wt[k][col] = w_in[col][k] * g_branch[k] (*invsqd for q cols)
__device__ float g_bias[768];
__device__ float g_WoT[256 * 256];   // WoT[k][j] = w_out[j][k]

typedef unsigned long long u64;

__device__ __forceinline__ u64 pk2(float lo, float hi) {
    u64 r; asm("mov.b64 %0, {%1, %2};" : "=l"(r) : "f"(lo), "f"(hi)); return r;
}
__device__ __forceinline__ void upk2(u64 v, float& lo, float& hi) {
    asm("mov.b64 {%0, %1}, %2;" : "=f"(lo), "=f"(hi) : "l"(v));
}
__device__ __forceinline__ void fma2(u64& d, u64 a, u64 b) {
    asm("fma.rn.f32x2 %0, %1, %2, %3;" : "=l"(d) : "l"(a), "l"(b), "l"(d));
}
__device__ __forceinline__ u64 add2(u64 a, u64 b) {
    u64 r; asm("add.rn.f32x2 %0, %1, %2;" : "=l"(r) : "l"(a), "l"(b)); return r;
}
__device__ __forceinline__ u64 lds2(const float* p) {
    return *reinterpret_cast<const u64*>(p);
}
__device__ __forceinline__ void sts2(float* p, u64 v) {
    *reinterpret_cast<u64*>(p) = v;
}

// ---- prep: fold LN affine (and q-scale) into packed in_proj, k-major ----
__global__ void prep_w_kernel(const float* __restrict__ w_in, const float* __restrict__ b_in,
                              const float* __restrict__ g_q, const float* __restrict__ b_q,
                              const float* __restrict__ g_k, const float* __restrict__ b_k,
                              const float* __restrict__ g_v, const float* __restrict__ b_v) {
    __shared__ float red[8];
    int col = blockIdx.x;       // 0..767
    int k   = threadIdx.x;      // 0..255
    const float* g; const float* b;
    if (col < 256)      { g = g_q; b = b_q; }
    else if (col < 512) { g = g_k; b = b_k; }
    else                { g = g_v; b = b_v; }
    const float f = (col < 256) ? 0.17677669529663689f : 1.0f;   // 1/sqrt(32) folded into q
    float w = w_in[col * 256 + k];
    g_Wt[k * 768 + col] = w * g[k] * f;
    float p = w * b[k];
    #pragma unroll
    for (int o = 16; o; o >>= 1) p += __shfl_xor_sync(0xffffffffu, p, o);
    if ((k & 31) == 0) red[k >> 5] = p;
    __syncthreads();
    if (k < 8) {
        float s = red[k];
        #pragma unroll
        for (int o = 4; o; o >>= 1) s += __shfl_xor_sync(0xffu, s, o);
        if (k == 0) g_bias[col] = (b_in[col] + s) * f;
    }
}

__global__ void prep_wo_kernel(const float* __restrict__ w_out) {
    int idx = blockIdx.x * 256 + threadIdx.x;   // 65536 elements
    int j = idx >> 8, k = idx & 255;
    g_WoT[k * 256 + j] = w_out[idx];
}

// ---- main fused window-attention kernel ----
// smem (floats):
//  xnp   [32][256][2]  pair-interleaved normalized input / residual   16384
//  obufp [32][256][2]  pair-interleaved attention output              16384
//  q2p   [32][65*2]    pair-interleaved q (2 heads, 64 cols, pad)      4160
//  k2    [64][65]      row-major k                                     4160
//  v2    [64][65]      row-major v                                     4160
//  scp   [32][65*2]    pair-interleaved scores                         4160
//  wbuf  double-buffered weight tiles (GEMM1: 2x1536, outproj: 2x2048) 4096
//  mA,sA [64] each                                                      128
__global__ __launch_bounds__(256, 1)
void win_attn_kernel(const float* __restrict__ x, const float* __restrict__ b_out,
                     const float* __restrict__ g_o, const float* __restrict__ b_o,
                     float* __restrict__ y) {
    extern __shared__ float sm[];
    float* xnp   = sm;             // 16384
    float* obufp = sm + 16384;     // 16384
    float* q2p   = sm + 32768;     // 4160
    float* k2    = sm + 36928;     // 4160
    float* v2    = sm + 41088;     // 4160
    float* scp   = sm + 45248;     // 4160
    float* wbuf  = sm + 49408;     // 4096
    float* mA    = sm + 53504;     // 64
    float* sA    = sm + 53568;     // 64   total 53632 floats = 214528 B

    const int tid  = threadIdx.x;
    const int w    = tid >> 5;
    const int tx   = tid & 31;
    const int row0 = w * 8;
    const int pg0  = w * 4;        // warp owns row-pairs pg0..pg0+3

    const int win = blockIdx.x;
    const int b   = win >> 6;
    const int wh  = (win >> 3) & 7;
    const int ww  = win & 7;
    const int gbase = ((b * 64 + wh * 8) * 64 + ww * 8) * 256;

    // ---- load window into pair-interleaved smem ----
    for (int t = 0; t < 64; ++t) {
        int off = gbase + (t >> 3) * (64 * 256) + (t & 7) * 256;
        xnp[(t >> 1) * 512 + tid * 2 + (t & 1)] = x[off + tid];
    }
    __syncthreads();

    // ---- LN stats + normalize in place (warp-local rows) ----
    for (int i = 0; i < 8; ++i) {
        int r = row0 + i;
        int base = (r >> 1) * 512 + (r & 1);
        float s = 0.f, ss = 0.f;
        #pragma unroll
        for (int c = tx; c < 256; c += 32) { float v = xnp[base + c * 2]; s += v; ss += v * v; }
        #pragma unroll
        for (int o = 16; o; o >>= 1) { s  += __shfl_xor_sync(0xffffffffu, s,  o);
                                       ss += __shfl_xor_sync(0xffffffffu, ss, o); }
        float mean = s * (1.f / 256.f);
        float var  = ss * (1.f / 256.f) - mean * mean;
        float sd   = sqrtf(var + EPS);
        float inv  = 1.f / sd;
        if (tx == 0) { mA[r] = mean; sA[r] = sd; }
        #pragma unroll
        for (int c = tx; c < 256; c += 32) xnp[base + c * 2] = (xnp[base + c * 2] - mean) * inv;
    }
    __syncthreads();

    for (int hp = 0; hp < 4; ++hp) {
        const int hA = hp, hB = hp + 4;
        const int cA = hA * 32 + tx, cB = hB * 32 + tx;

        // ---- GEMM1: q,k,v for heads hA,hB; weights staged in smem ----
        {
            u64 acc[4][6];
            #pragma unroll
            for (int p = 0; p < 4; ++p)
                #pragma unroll
                for (int j = 0; j < 6; ++j) acc[p][j] = 0ULL;

            // preload tile 0 (warp w stages kk row w of the tile; 6 segments)
            float st0, st1, st2, st3, st4, st5;
            {
                const float* wg = g_Wt + w * 768;
                st0 = wg[cA]; st1 = wg[256 + cA]; st2 = wg[512 + cA];
                st3 = wg[cB]; st4 = wg[256 + cB]; st5 = wg[512 + cB];
            }
            {
                float* wd = wbuf + w * 192;
                wd[tx] = st0; wd[32 + tx] = st1; wd[64 + tx] = st2;
                wd[96 + tx] = st3; wd[128 + tx] = st4; wd[160 + tx] = st5;
            }
            __syncthreads();

            const float* ap0 = xnp + (pg0 + 0) * 512;
            const float* ap1 = xnp + (pg0 + 1) * 512;
            const float* ap2 = xnp + (pg0 + 2) * 512;
            const float* ap3 = xnp + (pg0 + 3) * 512;

            for (int kt = 0; kt < 32; ++kt) {
                int cb = kt & 1, nb = cb ^ 1;
                if (kt < 31) {
                    const float* wg = g_Wt + ((kt + 1) * 8 + w) * 768;
                    st0 = wg[cA]; st1 = wg[256 + cA]; st2 = wg[512 + cA];
                    st3 = wg[cB]; st4 = wg[256 + cB]; st5 = wg[512 + cB];
                }
                const float* wt = wbuf + cb * 1536;
                #pragma unroll
                for (int kk = 0; kk < 8; ++kk) {
                    const float* wr = wt + kk * 192;
                    float w0 = wr[tx],      w1 = wr[32 + tx],  w2 = wr[64 + tx];
                    float w3 = wr[96 + tx], w4 = wr[128 + tx], w5 = wr[160 + tx];
                    u64 W0 = pk2(w0, w0), W1 = pk2(w1, w1), W2 = pk2(w2, w2);
                    u64 W3 = pk2(w3, w3), W4 = pk2(w4, w4), W5 = pk2(w5, w5);
                    const int kg2 = (kt * 8 + kk) * 2;
                    u64 A0 = lds2(ap0 + kg2), A1 = lds2(ap1 + kg2);
                    u64 A2 = lds2(ap2 + kg2), A3 = lds2(ap3 + kg2);
                    fma2(acc[0][0], A0, W0); fma2(acc[0][1], A0, W1); fma2(acc[0][2], A0, W2);
                    fma2(acc[0][3], A0, W3); fma2(acc[0][4], A0, W4); fma2(acc[0][5], A0, W5);
                    fma2(acc[1][0], A1, W0); fma2(acc[1][1], A1, W1); fma2(acc[1][2], A1, W2);
                    fma2(acc[1][3], A1, W3); fma2(acc[1][4], A1, W4); fma2(acc[1][5], A1, W5);
                    fma2(acc[2][0], A2, W0); fma2(acc[2][1], A2, W1); fma2(acc[2][2], A2, W2);
                    fma2(acc[2][3], A2, W3); fma2(acc[2][4], A2, W4); fma2(acc[2][5], A2, W5);
                    fma2(acc[3][0], A3, W0); fma2(acc[3][1], A3, W1); fma2(acc[3][2], A3, W2);
                    fma2(acc[3][3], A3, W3); fma2(acc[3][4], A3, W4); fma2(acc[3][5], A3, W5);
                }
                if (kt < 31) {
                    float* wd = wbuf + nb * 1536 + w * 192;
                    wd[tx] = st0; wd[32 + tx] = st1; wd[64 + tx] = st2;
                    wd[96 + tx] = st3; wd[128 + tx] = st4; wd[160 + tx] = st5;
                }
                __syncthreads();
            }

            // epilogue: add bias, store q (pairs), k/v (row-major)
            float bqa = g_bias[cA], bka = g_bias[256 + cA], bva = g_bias[512 + cA];
            float bqb = g_bias[cB], bkb = g_bias[256 + cB], bvb = g_bias[512 + cB];
            u64 BQA = pk2(bqa, bqa), BKA = pk2(bka, bka), BVA = pk2(bva, bva);
            u64 BQB = pk2(bqb, bqb), BKB = pk2(bkb, bkb), BVB = pk2(bvb, bvb);
            #pragma unroll
            for (int p = 0; p < 4; ++p) {
                int pg = pg0 + p, r0 = row0 + 2 * p, r1 = r0 + 1;
                float lo, hi;
                sts2(q2p + pg * 130 + tx * 2, add2(acc[p][0], BQA));
                sts2(q2p + pg * 130 + (32 + tx) * 2, add2(acc[p][3], BQB));
                upk2(add2(acc[p][1], BKA), lo, hi);
                k2[r0 * 65 + tx] = lo;        k2[r1 * 65 + tx] = hi;
                upk2(add2(acc[p][4], BKB), lo, hi);
                k2[r0 * 65 + 32 + tx] = lo;   k2[r1 * 65 + 32 + tx] = hi;
                upk2(add2(acc[p][2], BVA), lo, hi);
                v2[r0 * 65 + tx] = lo;        v2[r1 * 65 + tx] = hi;
                upk2(add2(acc[p][5], BVB), lo, hi);
                v2[r0 * 65 + 32 + tx] = lo;   v2[r1 * 65 + 32 + tx] = hi;
            }
        }
        __syncthreads();

        #pragma unroll
        for (int s = 0; s < 2; ++s) {
            const int hcol = (s == 0 ? hA : hB) * 32;
            const int kc0  = s * 32;
            // ---- GEMM2: scores, K=32 ----
            {
                u64 a2[4][2];
                #pragma unroll
                for (int p = 0; p < 4; ++p) { a2[p][0] = 0ULL; a2[p][1] = 0ULL; }
                #pragma unroll 4
                for (int kk = 0; kk < 32; ++kk) {
                    int kc = kc0 + kk;
                    float b0 = k2[tx * 65 + kc];
                    float b1 = k2[(tx + 32) * 65 + kc];
                    u64 B0 = pk2(b0, b0), B1 = pk2(b1, b1);
                    #pragma unroll
                    for (int p = 0; p < 4; ++p) {
                        u64 A = lds2(q2p + (pg0 + p) * 130 + kc * 2);
                        fma2(a2[p][0], A, B0); fma2(a2[p][1], A, B1);
                    }
                }
                #pragma unroll
                for (int p = 0; p < 4; ++p) {
                    sts2(scp + (pg0 + p) * 130 + tx * 2,        a2[p][0]);
                    sts2(scp + (pg0 + p) * 130 + (32 + tx) * 2, a2[p][1]);
                }
            }
            __syncwarp();
            // ---- softmax (warp-local rows) ----
            #pragma unroll
            for (int i = 0; i < 8; ++i) {
                int r = row0 + i;
                int sb = (r >> 1) * 130 + (r & 1);
                float s0 = scp[sb + tx * 2], s1 = scp[sb + (32 + tx) * 2];
                float mx = fmaxf(s0, s1);
                #pragma unroll
                for (int o = 16; o; o >>= 1) mx = fmaxf(mx, __shfl_xor_sync(0xffffffffu, mx, o));
                float e0 = __expf(s0 - mx), e1 = __expf(s1 - mx);
                float sum = e0 + e1;
                #pragma unroll
                for (int o = 16; o; o >>= 1) sum += __shfl_xor_sync(0xffffffffu, sum, o);
                float inv = 1.f / sum;
                scp[sb + tx * 2] = e0 * inv; scp[sb + (32 + tx) * 2] = e1 * inv;
            }
            __syncwarp();
            // ---- GEMM3: attn @ v, K=64 ----
            {
                u64 a3[4] = {0ULL, 0ULL, 0ULL, 0ULL};
                #pragma unroll 4
                for (int l = 0; l < 64; ++l) {
                    float bv = v2[l * 65 + kc0 + tx];
                    u64 B = pk2(bv, bv);
                    #pragma unroll
                    for (int p = 0; p < 4; ++p) {
                        u64 A = lds2(scp + (pg0 + p) * 130 + l * 2);
                        fma2(a3[p], A, B);
                    }
                }
                #pragma unroll
                for (int p = 0; p < 4; ++p)
                    sts2(obufp + (pg0 + p) * 512 + (hcol + tx) * 2, a3[p]);
            }
            __syncwarp();
        }
        __syncthreads();   // before next hp reuses q2p/k2/v2
    }

    // ---- out projection (smem-staged WoT tiles) + residual ----
    {
        u64 acc[4][8];
        #pragma unroll
        for (int p = 0; p < 4; ++p)
            #pragma unroll
            for (int j = 0; j < 8; ++j) acc[p][j] = 0ULL;

        float st[8];
        {
            const float* wg = g_WoT + w * 256;
            #pragma unroll
            for (int s2 = 0; s2 < 8; ++s2) st[s2] = wg[s2 * 32 + tx];
        }
        {
            float* wd = wbuf + w * 256;
            #pragma unroll
            for (int s2 = 0; s2 < 8; ++s2) wd[s2 * 32 + tx] = st[s2];
        }
        __syncthreads();

        const float* ap0 = obufp + (pg0 + 0) * 512;
        const float* ap1 = obufp + (pg0 + 1) * 512;
        const float* ap2 = obufp + (pg0 + 2) * 512;
        const float* ap3 = obufp + (pg0 + 3) * 512;

        for (int kt = 0; kt < 32; ++kt) {
            int cb = kt & 1, nb = cb ^ 1;
            if (kt < 31) {
                const float* wg = g_WoT + ((kt + 1) * 8 + w) * 256;
                #pragma unroll
                for (int s2 = 0; s2 < 8; ++s2) st[s2] = wg[s2 * 32 + tx];
            }
            const float* wt = wbuf + cb * 2048;
            #pragma unroll
            for (int kk = 0; kk < 8; ++kk) {
                const float* wr = wt + kk * 256;
                u64 W[8];
                #pragma unroll
                for (int j = 0; j < 8; ++j) { float wv = wr[j * 32 + tx]; W[j] = pk2(wv, wv); }
                const int kg2 = (kt * 8 + kk) * 2;
                u64 A0 = lds2(ap0 + kg2), A1 = lds2(ap1 + kg2);
                u64 A2 = lds2(ap2 + kg2), A3 = lds2(ap3 + kg2);
                #pragma unroll
                for (int j = 0; j < 8; ++j) fma2(acc[0][j], A0, W[j]);
                #pragma unroll
                for (int j = 0; j < 8; ++j) fma2(acc[1][j], A1, W[j]);
                #pragma unroll
                for (int j = 0; j < 8; ++j) fma2(acc[2][j], A2, W[j]);
                #pragma unroll
                for (int j = 0; j < 8; ++j) fma2(acc[3][j], A3, W[j]);
            }
            if (kt < 31) {
                float* wd = wbuf + nb * 2048 + w * 256;
                #pragma unroll
                for (int s2 = 0; s2 < 8; ++s2) wd[s2 * 32 + tx] = st[s2];
            }
            __syncthreads();
        }

        // residual: xn := xn*sd + mean + (o + b_out)   (pair ops)
        float bo[8];
        #pragma unroll
        for (int j = 0; j < 8; ++j) bo[j] = b_out[j * 32 + tx];
        #pragma unroll
        for (int p = 0; p < 4; ++p) {
            int pg = pg0 + p, r0 = row0 + 2 * p, r1 = r0 + 1;
            u64 S = pk2(sA[r0], sA[r1]);
            float m0 = mA[r0], m1 = mA[r1];
            #pragma unroll
            for (int j = 0; j < 8; ++j) {
                int c = j * 32 + tx;
                u64 t = acc[p][j];
                u64 X = lds2(xnp + pg * 512 + c * 2);
                fma2(t, X, S);                      // t = X*sd + o
                t = add2(t, pk2(m0 + bo[j], m1 + bo[j]));
                sts2(xnp + pg * 512 + c * 2, t);
            }
        }
    }
    __syncwarp();

    // ---- final LN + store ----
    for (int i = 0; i < 8; ++i) {
        int r = row0 + i;
        int base = (r >> 1) * 512 + (r & 1);
        float s = 0.f, ss = 0.f;
        #pragma unroll
        for (int c = tx; c < 256; c += 32) { float v = xnp[base + c * 2]; s += v; ss += v * v; }
        #pragma unroll
        for (int o = 16; o; o >>= 1) { s  += __shfl_xor_sync(0xffffffffu, s,  o);
                                       ss += __shfl_xor_sync(0xffffffffu, ss, o); }
        float mean = s * (1.f / 256.f);
        float var  = ss * (1.f / 256.f) - mean * mean;
        float inv  = rsqrtf(var + EPS);
        int off = gbase + (r >> 3) * (64 * 256) + (r & 7) * 256;
        #pragma unroll
        for (int c = tx; c < 256; c += 32) {
            float v = (xnp[base + c * 2] - mean) * inv;
            y[off + c] = v * g_o[c] + b_o[c];
        }
    }
}

static const int SMEM_BYTES = 53632 * (int)sizeof(float);   // 214528 B

extern "C" void kernel_launch(void* const* d_in, const int* in_sizes, int n_in,
                              void* d_out, int out_size) {
    (void)in_sizes; (void)n_in; (void)out_size;
    const float* x     = (const float*)d_in[0];
    const float* w_in  = (const float*)d_in[1];
    const float* b_in  = (const float*)d_in[2];
    const float* w_out = (const float*)d_in[3];
    const float* b_out = (const float*)d_in[4];
    const float* g_q   = (const float*)d_in[5];
    const float* b_q   = (const float*)d_in[6];
    const float* g_k   = (const float*)d_in[7];
    const float* b_k   = (const float*)d_in[8];
    const float* g_v   = (const float*)d_in[9];
    const float* b_v   = (const float*)d_in[10];
    const float* g_o   = (const float*)d_in[11];
    const float* b_o   = (const float*)d_in[12];
    float* y = (float*)d_out;

    cudaFuncSetAttribute(win_attn_kernel, cudaFuncAttributeMaxDynamicSharedMemorySize, SMEM_BYTES);

    prep_w_kernel<<<768, 256>>>(w_in, b_in, g_q, b_q, g_k, b_k, g_v, b_v);
    prep_wo_kernel<<<256, 256>>>(w_out);
    win_attn_kernel<<<2048, 256, SMEM_BYTES>>>(x, b_out, g_o, b_o, y);
}